// round 14
// baseline (speedup 1.0000x reference)
#include <cuda_runtime.h>
#include <math.h>

#define BZ 64       // batch
#define SQ 1024     // seq len
#define HD 512      // hidden
#define GT 2048     // 4*H
#define KD 512      // input size
#define NCTA 128    // persistent CTAs in recurrence

// Static device scratch (cudaMalloc banned)
__device__ float g_xW[(size_t)SQ * GT * BZ];   // [s][n][b]
__device__ float g_h[2][BZ * KD];              // [b][k], full fp32 state
__device__ unsigned g_flag[(SQ + 1) * NCTA];   // per-step per-CTA arrival flags

// ---------------- tf32 mask split (proven R5/R7/R10) -----------------------
__device__ __forceinline__ float tf32_hi(float v) {
    return __uint_as_float(__float_as_uint(v) & 0xFFFFE000u);
}
__device__ __forceinline__ void mma8(float* d, const unsigned* a, const unsigned* b) {
    asm volatile("mma.sync.aligned.m16n8k8.row.col.f32.tf32.tf32.f32 "
                 "{%0,%1,%2,%3}, {%4,%5,%6,%7}, {%8,%9}, {%0,%1,%2,%3};\n"
                 : "+f"(d[0]), "+f"(d[1]), "+f"(d[2]), "+f"(d[3])
                 : "r"(a[0]), "r"(a[1]), "r"(a[2]), "r"(a[3]), "r"(b[0]), "r"(b[1]));
}
__device__ __forceinline__ float sigmoidf_(float v) { return 1.f / (1.f + __expf(-v)); }
__device__ __forceinline__ float tanh_fast(float v) {
    float r; asm("tanh.approx.f32 %0, %1;" : "=f"(r) : "f"(v)); return r;
}
__device__ __forceinline__ unsigned ld_acq(const unsigned* p) {
    unsigned v; asm volatile("ld.acquire.gpu.global.u32 %0, [%1];" : "=r"(v) : "l"(p) : "memory");
    return v;
}
__device__ __forceinline__ void st_rel(unsigned* p, unsigned v) {
    asm volatile("st.release.gpu.global.u32 [%0], %1;" :: "l"(p), "r"(v) : "memory");
}
// cp.async.cg: 16B global->shared, L2-only on the read path (L1 bypass ->
// coherent with release/acquire protocol; .ca would NOT be -- R4's bug).
__device__ __forceinline__ void cp_async_cg16(float* smem_dst, const float* gsrc) {
    unsigned daddr = (unsigned)__cvta_generic_to_shared(smem_dst);
    asm volatile("cp.async.cg.shared.global [%0], [%1], 16;" :: "r"(daddr), "l"(gsrc));
}

// ---------------------------------------------------------------------------
// Phase 1 (tf32 tensor cores, 3-term mask split) + folded init. PROVEN R10.
// xW[s][n][b] = x @ W + bias.  CTA tile: M=128 (2s x 64b), N=128, k-chunk 32.
// ---------------------------------------------------------------------------
__global__ __launch_bounds__(256) void xw_gemm_tc(const float* __restrict__ x,
                                                  const float* __restrict__ W,
                                                  const float* __restrict__ bias) {
    extern __shared__ float sm1[];
    float* sXh = sm1;                 // [128][36]  x hi, row-major [m][k]
    float* sXl = sXh + 128 * 36;      // [128][36]  x lo
    float* sWh = sXl + 128 * 36;      // [32][132]  W hi, k-major [k][n]
    float* sWl = sWh + 32 * 132;      // [32][132]  W lo
    float* sB  = sWl + 32 * 132;      // [128]

    const int tid = threadIdx.x;
    const int s0 = blockIdx.y * 2;
    const int n0 = blockIdx.x * 128;
    const int w = tid >> 5, lane = tid & 31;
    const int r = lane >> 2, cq = lane & 3;
    const int m0w = (w & 1) * 64;
    const int n0w = (w >> 1) * 32;

    if (blockIdx.y == 0) {            // folded init (16 CTAs, 4096 threads)
        int gtid = blockIdx.x * 256 + tid;
        for (int i = gtid; i < 2 * BZ * KD; i += 4096) ((float*)g_h)[i] = 0.f;
        for (int i = gtid; i < (SQ + 1) * NCTA; i += 4096) g_flag[i] = 0u;
    }

    if (tid < 128) sB[tid] = bias[n0 + tid];

    float acc[4][4][4] = {};

    for (int k0 = 0; k0 < KD; k0 += 32) {
        #pragma unroll
        for (int i = 0; i < 4; i++) {
            int idx = i * 256 + tid;
            int row = idx >> 3, kf = (idx & 7) * 4;
            int b = row & 63, sL = row >> 6;
            float4 v = *(const float4*)(x + ((size_t)b * SQ + s0 + sL) * KD + k0 + kf);
            float4 h4 = make_float4(tf32_hi(v.x), tf32_hi(v.y), tf32_hi(v.z), tf32_hi(v.w));
            float4 l4 = make_float4(v.x - h4.x, v.y - h4.y, v.z - h4.z, v.w - h4.w);
            *(float4*)(sXh + row * 36 + kf) = h4;
            *(float4*)(sXl + row * 36 + kf) = l4;
        }
        #pragma unroll
        for (int i = 0; i < 4; i++) {
            int idx = i * 256 + tid;
            int kk = idx >> 5, nn = (idx & 31) * 4;
            float4 v = *(const float4*)(W + (size_t)(k0 + kk) * GT + n0 + nn);
            float4 h4 = make_float4(tf32_hi(v.x), tf32_hi(v.y), tf32_hi(v.z), tf32_hi(v.w));
            float4 l4 = make_float4(v.x - h4.x, v.y - h4.y, v.z - h4.z, v.w - h4.w);
            *(float4*)(sWh + kk * 132 + nn) = h4;
            *(float4*)(sWl + kk * 132 + nn) = l4;
        }
        __syncthreads();

        #pragma unroll
        for (int kt = 0; kt < 4; kt++) {
            int kb = kt * 8;
            unsigned bh[4][2], bl[4][2];
            #pragma unroll
            for (int ni = 0; ni < 4; ni++) {
                int nn = n0w + ni * 8 + r;
                bh[ni][0] = __float_as_uint(sWh[(kb + cq) * 132 + nn]);
                bh[ni][1] = __float_as_uint(sWh[(kb + cq + 4) * 132 + nn]);
                bl[ni][0] = __float_as_uint(sWl[(kb + cq) * 132 + nn]);
                bl[ni][1] = __float_as_uint(sWl[(kb + cq + 4) * 132 + nn]);
            }
            #pragma unroll
            for (int mi = 0; mi < 4; mi++) {
                const float* ah = sXh + (m0w + mi * 16) * 36 + kb;
                const float* al = sXl + (m0w + mi * 16) * 36 + kb;
                unsigned afh[4] = {__float_as_uint(ah[r * 36 + cq]),
                                   __float_as_uint(ah[(r + 8) * 36 + cq]),
                                   __float_as_uint(ah[r * 36 + cq + 4]),
                                   __float_as_uint(ah[(r + 8) * 36 + cq + 4])};
                unsigned afl[4] = {__float_as_uint(al[r * 36 + cq]),
                                   __float_as_uint(al[(r + 8) * 36 + cq]),
                                   __float_as_uint(al[r * 36 + cq + 4]),
                                   __float_as_uint(al[(r + 8) * 36 + cq + 4])};
                #pragma unroll
                for (int ni = 0; ni < 4; ni++) {
                    mma8(acc[mi][ni], afh, bh[ni]);
                    mma8(acc[mi][ni], afl, bh[ni]);
                    mma8(acc[mi][ni], afh, bl[ni]);
                }
            }
        }
        __syncthreads();
    }

    #pragma unroll
    for (int mi = 0; mi < 4; mi++)
        #pragma unroll
        for (int ni = 0; ni < 4; ni++) {
            int n = n0w + ni * 8 + cq * 2;
            float b0v = sB[n], b1v = sB[n + 1];
            int m = m0w + mi * 16 + r;
            {
                int sL = m >> 6, b = m & 63;
                size_t base = ((size_t)(s0 + sL) * GT + n0 + n) * BZ + b;
                g_xW[base]      = acc[mi][ni][0] + b0v;
                g_xW[base + BZ] = acc[mi][ni][1] + b1v;
            }
            {
                int m2 = m + 8;
                int sL = m2 >> 6, b = m2 & 63;
                size_t base = ((size_t)(s0 + sL) * GT + n0 + n) * BZ + b;
                g_xW[base]      = acc[mi][ni][2] + b0v;
                g_xW[base + BZ] = acc[mi][ni][3] + b1v;
            }
        }
}

// ---------------------------------------------------------------------------
// Phase 2: persistent recurrence, tf32 mma (mask split, 3 terms).
// h staged via cp.async.cg in 2 k-chunks (2 commit groups): zero register
// cost, chunk-1 latency hides under chunk-0 MMA. MMA math identical to R10.
// ---------------------------------------------------------------------------
#define HSTR2 260   // h chunk row stride (floats): 256 + 4 pad
#define BSTR 1040   // interleaved U row stride (floats), proven R5/R7/R10

__global__ __launch_bounds__(256, 1) void lstm_rec(const float* __restrict__ U,
                                                   float* __restrict__ out, int has_hc) {
    extern __shared__ float sm[];
    float* hA = sm;                       // [2][64][HSTR2] h chunks (k 0..255, 256..511)
    float* hU = hA + 2 * 64 * HSTR2;      // [16][BSTR] resident U hi/lo interleaved
    float* sg = hU + 16 * BSTR;           // [64][17]   gate staging

    const int tid = threadIdx.x;
    const int hc0 = blockIdx.x * 4;
    const int w = tid >> 5, lane = tid & 31;
    const int r = lane >> 2, cq = lane & 3;
    const int m0 = (w & 3) * 16;          // warp batch base
    const int col0 = (w >> 2) * 8;        // warp gate-col base

    const int eb = tid & 63;              // elementwise: batch
    const int jl = tid >> 6;              // elementwise: local h-col
    const int j = hc0 + jl;

    // resident interleaved U (hi,lo): per 8-k block, 16 floats
    // (hi[q],lo[q],hi[q+4],lo[q+4]) at offset q*4 + half*2
    for (int idx = tid; idx < 16 * KD; idx += 256) {
        int col = idx >> 9, k = idx & (KD - 1);
        int gc = (col >> 2) * HD + hc0 + (col & 3);
        float u = __ldg(U + (size_t)k * GT + gc);
        float hi = tf32_hi(u);
        float lo = u - hi;
        int off = (k >> 3) * 16 + (k & 3) * 4 + ((k >> 2) & 1) * 2;
        *(float2*)(hU + col * BSTR + off) = make_float2(hi, lo);
    }
    float c_reg = 0.f;

    float* out_hs = out;                               // [B][S][H]
    float* out_ht = out + (size_t)BZ * SQ * HD;
    float* out_ct = out_ht + (size_t)BZ * HD;

    __syncthreads();

    for (int t = 0; t < SQ; t++) {
        // xW gate terms -- independent of h, load before the wait
        float xwv[4];
        #pragma unroll
        for (int g = 0; g < 4; g++)
            xwv[g] = __ldcs(g_xW + ((size_t)t * GT + g * HD + j) * BZ + eb);

        if (t > 0) {
            if (tid < NCTA) {
                const unsigned* f = &g_flag[(size_t)t * NCTA + tid];
                while (ld_acq(f) == 0u) { }
            }
            __syncthreads();
        }

        const float* hsrc = g_h[t & 1];

        // issue both h chunks as cp.async.cg (no register cost)
        #pragma unroll
        for (int c = 0; c < 2; c++) {
            float* hAc = hA + c * 64 * HSTR2;
            #pragma unroll
            for (int i = 0; i < 16; i++) {
                int idx = i * 256 + tid;
                int b = idx >> 6, kf4 = idx & 63;
                cp_async_cg16(hAc + b * HSTR2 + kf4 * 4,
                              hsrc + b * KD + c * 256 + kf4 * 4);
            }
            asm volatile("cp.async.commit_group;");
        }

        float aA[2][4] = {}, aB[2][4] = {}, aC[2][4] = {};

        // ---- chunk 0: wait for group 0 (<=1 pending), MMA ----
        asm volatile("cp.async.wait_group 1;");
        __syncthreads();
        {
            const float* arow0 = hA + (m0 + r) * HSTR2;
            const float* arow1 = hA + (m0 + r + 8) * HSTR2;
            const float* brow  = hU + (col0 + r) * BSTR;
            #pragma unroll 4
            for (int kt = 0; kt < 32; kt++) {
                int kb = kt * 8;
                float f0 = arow0[kb + cq],     f1 = arow1[kb + cq];
                float f2 = arow0[kb + cq + 4], f3 = arow1[kb + cq + 4];
                float h0 = tf32_hi(f0), h1 = tf32_hi(f1), h2 = tf32_hi(f2), h3 = tf32_hi(f3);
                unsigned ahi[4] = {__float_as_uint(h0), __float_as_uint(h1),
                                   __float_as_uint(h2), __float_as_uint(h3)};
                unsigned alo[4] = {__float_as_uint(f0 - h0), __float_as_uint(f1 - h1),
                                   __float_as_uint(f2 - h2), __float_as_uint(f3 - h3)};
                float4 Bv = *(const float4*)(brow + kt * 16 + cq * 4);
                unsigned bhi[2] = {__float_as_uint(Bv.x), __float_as_uint(Bv.z)};
                unsigned blo[2] = {__float_as_uint(Bv.y), __float_as_uint(Bv.w)};
                int p = kt & 1;
                mma8(aA[p], ahi, bhi);
                mma8(aB[p], alo, bhi);
                mma8(aC[p], ahi, blo);
            }
        }

        // ---- chunk 1: wait all, MMA ----
        asm volatile("cp.async.wait_group 0;");
        __syncthreads();
        {
            const float* arow0 = hA + 64 * HSTR2 + (m0 + r) * HSTR2;
            const float* arow1 = hA + 64 * HSTR2 + (m0 + r + 8) * HSTR2;
            const float* brow  = hU + (col0 + r) * BSTR + 512;
            #pragma unroll 4
            for (int kt = 0; kt < 32; kt++) {
                int kb = kt * 8;
                float f0 = arow0[kb + cq],     f1 = arow1[kb + cq];
                float f2 = arow0[kb + cq + 4], f3 = arow1[kb + cq + 4];
                float h0 = tf32_hi(f0), h1 = tf32_hi(f1), h2 = tf32_hi(f2), h3 = tf32_hi(f3);
                unsigned ahi[4] = {__float_as_uint(h0), __float_as_uint(h1),
                                   __float_as_uint(h2), __float_as_uint(h3)};
                unsigned alo[4] = {__float_as_uint(f0 - h0), __float_as_uint(f1 - h1),
                                   __float_as_uint(f2 - h2), __float_as_uint(f3 - h3)};
                float4 Bv = *(const float4*)(brow + kt * 16 + cq * 4);
                unsigned bhi[2] = {__float_as_uint(Bv.x), __float_as_uint(Bv.z)};
                unsigned blo[2] = {__float_as_uint(Bv.y), __float_as_uint(Bv.w)};
                int p = kt & 1;
                mma8(aA[p], ahi, bhi);
                mma8(aB[p], alo, bhi);
                mma8(aC[p], ahi, blo);
            }
        }

        // combine, stage C frag -> sg[b][col]
        {
            float c0 = aA[0][0] + aB[0][0] + aC[0][0] + aA[1][0] + aB[1][0] + aC[1][0];
            float c1 = aA[0][1] + aB[0][1] + aC[0][1] + aA[1][1] + aB[1][1] + aC[1][1];
            float c2 = aA[0][2] + aB[0][2] + aC[0][2] + aA[1][2] + aB[1][2] + aC[1][2];
            float c3 = aA[0][3] + aB[0][3] + aC[0][3] + aA[1][3] + aB[1][3] + aC[1][3];
            int row0 = m0 + r, colb = col0 + cq * 2;
            sg[row0 * 17 + colb]           = c0;
            sg[row0 * 17 + colb + 1]       = c1;
            sg[(row0 + 8) * 17 + colb]     = c2;
            sg[(row0 + 8) * 17 + colb + 1] = c3;
        }
        __syncthreads();

        float gate[4];
        #pragma unroll
        for (int g = 0; g < 4; g++)
            gate[g] = xwv[g] + sg[eb * 17 + g * 4 + jl];

        float ig = sigmoidf_(gate[0]);
        float fg = sigmoidf_(gate[1]);
        float gg = tanh_fast(gate[2]);
        float og = sigmoidf_(gate[3]);
        c_reg = fg * c_reg + ig * gg;
        float hv = og * tanh_fast(c_reg);

        // publish h, then release-store the flag (orders prior stores)
        g_h[(t + 1) & 1][eb * KD + j] = hv;
        __syncthreads();
        if (tid == 0) st_rel(&g_flag[(size_t)(t + 1) * NCTA + blockIdx.x], 1u);

        // off-critical-path outputs
        out_hs[((size_t)eb * SQ + t) * HD + j] = hv;
        if (has_hc && t == SQ - 1) {
            out_ht[(size_t)eb * HD + j] = hv;
            out_ct[(size_t)eb * HD + j] = c_reg;
        }
    }
}

// ---------------------------------------------------------------------------
extern "C" void kernel_launch(void* const* d_in, const int* in_sizes, int n_in,
                              void* d_out, int out_size) {
    const float* x    = (const float*)d_in[0];
    const float* W    = (const float*)d_in[1];
    const float* U    = (const float*)d_in[2];
    const float* bias = (const float*)d_in[3];
    float* out = (float*)d_out;

    const int smem1 = (2 * 128 * 36 + 2 * 32 * 132 + 128) * (int)sizeof(float);    // 71,168 B
    const int smem2 = (2 * 64 * HSTR2 + 16 * BSTR + 64 * 17) * (int)sizeof(float); // 204,032 B
    cudaFuncSetAttribute(xw_gemm_tc, cudaFuncAttributeMaxDynamicSharedMemorySize, smem1);
    cudaFuncSetAttribute(lstm_rec, cudaFuncAttributeMaxDynamicSharedMemorySize, smem2);

    int has_hc = (out_size >= (int)((size_t)BZ * SQ * HD + 2 * BZ * HD)) ? 1 : 0;

    xw_gemm_tc<<<dim3(GT / 128, SQ / 2), 256, smem1>>>(x, W, bias);
    lstm_rec<<<NCTA, 256, smem2>>>(U, out, has_hc);
}

// round 15
// speedup vs baseline: 1.2172x; 1.2172x over previous
#include <cuda_runtime.h>
#include <math.h>

#define BZ 64       // batch
#define SQ 1024     // seq len
#define HD 512      // hidden
#define GT 2048     // 4*H
#define KD 512      // input size
#define NCTA 128    // persistent CTAs in recurrence

// Static device scratch (cudaMalloc banned)
__device__ float g_xW[(size_t)SQ * GT * BZ];   // [s][n][b]
__device__ float g_h[2][BZ * KD];              // [b][k], full fp32 state
__device__ unsigned g_flag[(SQ + 1) * NCTA];   // per-step per-CTA arrival flags

// ---------------- tf32 mask split (proven R5/R7/R10/R14) -------------------
__device__ __forceinline__ float tf32_hi(float v) {
    return __uint_as_float(__float_as_uint(v) & 0xFFFFE000u);
}
__device__ __forceinline__ void mma8(float* d, const unsigned* a, const unsigned* b) {
    asm volatile("mma.sync.aligned.m16n8k8.row.col.f32.tf32.tf32.f32 "
                 "{%0,%1,%2,%3}, {%4,%5,%6,%7}, {%8,%9}, {%0,%1,%2,%3};\n"
                 : "+f"(d[0]), "+f"(d[1]), "+f"(d[2]), "+f"(d[3])
                 : "r"(a[0]), "r"(a[1]), "r"(a[2]), "r"(a[3]), "r"(b[0]), "r"(b[1]));
}
__device__ __forceinline__ float sigmoidf_(float v) { return 1.f / (1.f + __expf(-v)); }
__device__ __forceinline__ float tanh_fast(float v) {
    float r; asm("tanh.approx.f32 %0, %1;" : "=f"(r) : "f"(v)); return r;
}
__device__ __forceinline__ unsigned ld_acq(const unsigned* p) {
    unsigned v; asm volatile("ld.acquire.gpu.global.u32 %0, [%1];" : "=r"(v) : "l"(p) : "memory");
    return v;
}
__device__ __forceinline__ void st_rel(unsigned* p, unsigned v) {
    asm volatile("st.release.gpu.global.u32 [%0], %1;" :: "l"(p), "r"(v) : "memory");
}

// ---------------------------------------------------------------------------
// Phase 1 (tf32 tensor cores, 3-term mask split) + folded init. PROVEN R10/R14.
// xW[s][n][b] = x @ W + bias.  CTA tile: M=128 (2s x 64b), N=128, k-chunk 32.
// ---------------------------------------------------------------------------
__global__ __launch_bounds__(256) void xw_gemm_tc(const float* __restrict__ x,
                                                  const float* __restrict__ W,
                                                  const float* __restrict__ bias) {
    extern __shared__ float sm1[];
    float* sXh = sm1;                 // [128][36]  x hi, row-major [m][k]
    float* sXl = sXh + 128 * 36;      // [128][36]  x lo
    float* sWh = sXl + 128 * 36;      // [32][132]  W hi, k-major [k][n]
    float* sWl = sWh + 32 * 132;      // [32][132]  W lo
    float* sB  = sWl + 32 * 132;      // [128]

    const int tid = threadIdx.x;
    const int s0 = blockIdx.y * 2;
    const int n0 = blockIdx.x * 128;
    const int w = tid >> 5, lane = tid & 31;
    const int r = lane >> 2, cq = lane & 3;
    const int m0w = (w & 1) * 64;
    const int n0w = (w >> 1) * 32;

    if (blockIdx.y == 0) {            // folded init (16 CTAs, 4096 threads)
        int gtid = blockIdx.x * 256 + tid;
        for (int i = gtid; i < 2 * BZ * KD; i += 4096) ((float*)g_h)[i] = 0.f;
        for (int i = gtid; i < (SQ + 1) * NCTA; i += 4096) g_flag[i] = 0u;
    }

    if (tid < 128) sB[tid] = bias[n0 + tid];

    float acc[4][4][4] = {};

    for (int k0 = 0; k0 < KD; k0 += 32) {
        #pragma unroll
        for (int i = 0; i < 4; i++) {
            int idx = i * 256 + tid;
            int row = idx >> 3, kf = (idx & 7) * 4;
            int b = row & 63, sL = row >> 6;
            float4 v = *(const float4*)(x + ((size_t)b * SQ + s0 + sL) * KD + k0 + kf);
            float4 h4 = make_float4(tf32_hi(v.x), tf32_hi(v.y), tf32_hi(v.z), tf32_hi(v.w));
            float4 l4 = make_float4(v.x - h4.x, v.y - h4.y, v.z - h4.z, v.w - h4.w);
            *(float4*)(sXh + row * 36 + kf) = h4;
            *(float4*)(sXl + row * 36 + kf) = l4;
        }
        #pragma unroll
        for (int i = 0; i < 4; i++) {
            int idx = i * 256 + tid;
            int kk = idx >> 5, nn = (idx & 31) * 4;
            float4 v = *(const float4*)(W + (size_t)(k0 + kk) * GT + n0 + nn);
            float4 h4 = make_float4(tf32_hi(v.x), tf32_hi(v.y), tf32_hi(v.z), tf32_hi(v.w));
            float4 l4 = make_float4(v.x - h4.x, v.y - h4.y, v.z - h4.z, v.w - h4.w);
            *(float4*)(sWh + kk * 132 + nn) = h4;
            *(float4*)(sWl + kk * 132 + nn) = l4;
        }
        __syncthreads();

        #pragma unroll
        for (int kt = 0; kt < 4; kt++) {
            int kb = kt * 8;
            unsigned bh[4][2], bl[4][2];
            #pragma unroll
            for (int ni = 0; ni < 4; ni++) {
                int nn = n0w + ni * 8 + r;
                bh[ni][0] = __float_as_uint(sWh[(kb + cq) * 132 + nn]);
                bh[ni][1] = __float_as_uint(sWh[(kb + cq + 4) * 132 + nn]);
                bl[ni][0] = __float_as_uint(sWl[(kb + cq) * 132 + nn]);
                bl[ni][1] = __float_as_uint(sWl[(kb + cq + 4) * 132 + nn]);
            }
            #pragma unroll
            for (int mi = 0; mi < 4; mi++) {
                const float* ah = sXh + (m0w + mi * 16) * 36 + kb;
                const float* al = sXl + (m0w + mi * 16) * 36 + kb;
                unsigned afh[4] = {__float_as_uint(ah[r * 36 + cq]),
                                   __float_as_uint(ah[(r + 8) * 36 + cq]),
                                   __float_as_uint(ah[r * 36 + cq + 4]),
                                   __float_as_uint(ah[(r + 8) * 36 + cq + 4])};
                unsigned afl[4] = {__float_as_uint(al[r * 36 + cq]),
                                   __float_as_uint(al[(r + 8) * 36 + cq]),
                                   __float_as_uint(al[r * 36 + cq + 4]),
                                   __float_as_uint(al[(r + 8) * 36 + cq + 4])};
                #pragma unroll
                for (int ni = 0; ni < 4; ni++) {
                    mma8(acc[mi][ni], afh, bh[ni]);
                    mma8(acc[mi][ni], afl, bh[ni]);
                    mma8(acc[mi][ni], afh, bl[ni]);
                }
            }
        }
        __syncthreads();
    }

    #pragma unroll
    for (int mi = 0; mi < 4; mi++)
        #pragma unroll
        for (int ni = 0; ni < 4; ni++) {
            int n = n0w + ni * 8 + cq * 2;
            float b0v = sB[n], b1v = sB[n + 1];
            int m = m0w + mi * 16 + r;
            {
                int sL = m >> 6, b = m & 63;
                size_t base = ((size_t)(s0 + sL) * GT + n0 + n) * BZ + b;
                g_xW[base]      = acc[mi][ni][0] + b0v;
                g_xW[base + BZ] = acc[mi][ni][1] + b1v;
            }
            {
                int m2 = m + 8;
                int sL = m2 >> 6, b = m2 & 63;
                size_t base = ((size_t)(s0 + sL) * GT + n0 + n) * BZ + b;
                g_xW[base]      = acc[mi][ni][2] + b0v;
                g_xW[base + BZ] = acc[mi][ni][3] + b1v;
            }
        }
}

// ---------------------------------------------------------------------------
// Phase 2: persistent recurrence -- R7's PROVEN fastest structure (7.8us/step):
// single full-K h stage (LDG->STS, one sync), inline mask-split A frags,
// resident interleaved U, 6 independent accumulators. Only deltas vs R7:
// xW prefetch before the flag wait; acquire/release sync (no threadfence).
// ---------------------------------------------------------------------------
#define HSTR 516    // raw h row stride (floats)
#define BSTR 1040   // interleaved U row stride (floats)

__global__ __launch_bounds__(256, 1) void lstm_rec(const float* __restrict__ U,
                                                   float* __restrict__ out, int has_hc) {
    extern __shared__ float sm[];
    float* hs = sm;                       // [64][HSTR] raw fp32 h (full K)
    float* hU = hs + 64 * HSTR;           // [16][BSTR] resident U hi/lo interleaved
    float* sg = hU + 16 * BSTR;           // [64][17]   gate staging

    const int tid = threadIdx.x;
    const int hc0 = blockIdx.x * 4;
    const int w = tid >> 5, lane = tid & 31;
    const int r = lane >> 2, cq = lane & 3;
    const int m0 = (w & 3) * 16;          // warp batch base (4 x 2 warp grid)
    const int col0 = (w >> 2) * 8;        // warp gate-col base

    const int eb = tid & 63;              // elementwise: batch
    const int jl = tid >> 6;              // elementwise: local h-col
    const int j = hc0 + jl;

    // resident interleaved U (hi,lo): per 8-k block, 16 floats
    // (hi[q],lo[q],hi[q+4],lo[q+4]) at offset q*4 + half*2
    for (int idx = tid; idx < 16 * KD; idx += 256) {
        int col = idx >> 9, k = idx & (KD - 1);
        int gc = (col >> 2) * HD + hc0 + (col & 3);
        float u = __ldg(U + (size_t)k * GT + gc);
        float hi = tf32_hi(u);
        float lo = u - hi;
        int off = (k >> 3) * 16 + (k & 3) * 4 + ((k >> 2) & 1) * 2;
        *(float2*)(hU + col * BSTR + off) = make_float2(hi, lo);
    }
    float c_reg = 0.f;

    float* out_hs = out;                               // [B][S][H]
    float* out_ht = out + (size_t)BZ * SQ * HD;
    float* out_ct = out_ht + (size_t)BZ * HD;

    __syncthreads();

    for (int t = 0; t < SQ; t++) {
        // xW gate terms -- independent of h, load before the wait
        float xwv[4];
        #pragma unroll
        for (int g = 0; g < 4; g++)
            xwv[g] = __ldcs(g_xW + ((size_t)t * GT + g * HD + j) * BZ + eb);

        if (t > 0) {
            if (tid < NCTA) {
                const unsigned* f = &g_flag[(size_t)t * NCTA + tid];
                while (ld_acq(f) == 0u) { }
            }
            __syncthreads();
        }

        // stage full raw h (64 x 512 = 128 KB) -- 32 coalesced float4/thread
        const float* hsrc = g_h[t & 1];
        #pragma unroll 8
        for (int i = 0; i < 32; i++) {
            int idx = i * 256 + tid;
            int b = idx >> 7, kf4 = idx & 127;
            float4 v = __ldcg((const float4*)(hsrc + b * KD + kf4 * 4));
            *(float4*)(hs + b * HSTR + kf4 * 4) = v;
        }
        __syncthreads();

        // MMA: 64 k-tiles, 2-way k-split, 3 split terms -> 6 indep accumulators
        float aA0[4] = {}, aB0[4] = {}, aC0[4] = {};
        float aA1[4] = {}, aB1[4] = {}, aC1[4] = {};
        const float* arow0 = hs + (m0 + r) * HSTR;
        const float* arow1 = hs + (m0 + r + 8) * HSTR;
        const float* brow  = hU + (col0 + r) * BSTR;
        #pragma unroll 4
        for (int kk = 0; kk < 32; kk++) {
            // ---- k-half 0: tile kk ----
            {
                int kb = kk * 8;
                float f0 = arow0[kb + cq],     f1 = arow1[kb + cq];
                float f2 = arow0[kb + cq + 4], f3 = arow1[kb + cq + 4];
                float h0 = tf32_hi(f0), h1 = tf32_hi(f1), h2 = tf32_hi(f2), h3 = tf32_hi(f3);
                unsigned ahi[4] = {__float_as_uint(h0), __float_as_uint(h1),
                                   __float_as_uint(h2), __float_as_uint(h3)};
                unsigned alo[4] = {__float_as_uint(f0 - h0), __float_as_uint(f1 - h1),
                                   __float_as_uint(f2 - h2), __float_as_uint(f3 - h3)};
                float4 Bv = *(const float4*)(brow + kk * 16 + cq * 4);
                unsigned bhi[2] = {__float_as_uint(Bv.x), __float_as_uint(Bv.z)};
                unsigned blo[2] = {__float_as_uint(Bv.y), __float_as_uint(Bv.w)};
                mma8(aA0, ahi, bhi);
                mma8(aB0, alo, bhi);
                mma8(aC0, ahi, blo);
            }
            // ---- k-half 1: tile kk+32 ----
            {
                int kb = (kk + 32) * 8;
                float f0 = arow0[kb + cq],     f1 = arow1[kb + cq];
                float f2 = arow0[kb + cq + 4], f3 = arow1[kb + cq + 4];
                float h0 = tf32_hi(f0), h1 = tf32_hi(f1), h2 = tf32_hi(f2), h3 = tf32_hi(f3);
                unsigned ahi[4] = {__float_as_uint(h0), __float_as_uint(h1),
                                   __float_as_uint(h2), __float_as_uint(h3)};
                unsigned alo[4] = {__float_as_uint(f0 - h0), __float_as_uint(f1 - h1),
                                   __float_as_uint(f2 - h2), __float_as_uint(f3 - h3)};
                float4 Bv = *(const float4*)(brow + (kk + 32) * 16 + cq * 4);
                unsigned bhi[2] = {__float_as_uint(Bv.x), __float_as_uint(Bv.z)};
                unsigned blo[2] = {__float_as_uint(Bv.y), __float_as_uint(Bv.w)};
                mma8(aA1, ahi, bhi);
                mma8(aB1, alo, bhi);
                mma8(aC1, ahi, blo);
            }
        }

        // combine and stage C frag -> sg[b][col]
        {
            float c0 = aA0[0] + aB0[0] + aC0[0] + aA1[0] + aB1[0] + aC1[0];
            float c1 = aA0[1] + aB0[1] + aC0[1] + aA1[1] + aB1[1] + aC1[1];
            float c2 = aA0[2] + aB0[2] + aC0[2] + aA1[2] + aB1[2] + aC1[2];
            float c3 = aA0[3] + aB0[3] + aC0[3] + aA1[3] + aB1[3] + aC1[3];
            int row0 = m0 + r, colb = col0 + cq * 2;
            sg[row0 * 17 + colb]           = c0;
            sg[row0 * 17 + colb + 1]       = c1;
            sg[(row0 + 8) * 17 + colb]     = c2;
            sg[(row0 + 8) * 17 + colb + 1] = c3;
        }
        __syncthreads();

        float gate[4];
        #pragma unroll
        for (int g = 0; g < 4; g++)
            gate[g] = xwv[g] + sg[eb * 17 + g * 4 + jl];

        float ig = sigmoidf_(gate[0]);
        float fg = sigmoidf_(gate[1]);
        float gg = tanh_fast(gate[2]);
        float og = sigmoidf_(gate[3]);
        c_reg = fg * c_reg + ig * gg;
        float hv = og * tanh_fast(c_reg);

        // publish h, then release-store the flag (orders prior global stores)
        g_h[(t + 1) & 1][eb * KD + j] = hv;
        __syncthreads();
        if (tid == 0) st_rel(&g_flag[(size_t)(t + 1) * NCTA + blockIdx.x], 1u);

        // off-critical-path outputs
        out_hs[((size_t)eb * SQ + t) * HD + j] = hv;
        if (has_hc && t == SQ - 1) {
            out_ht[(size_t)eb * HD + j] = hv;
            out_ct[(size_t)eb * HD + j] = c_reg;
        }
    }
}

// ---------------------------------------------------------------------------
extern "C" void kernel_launch(void* const* d_in, const int* in_sizes, int n_in,
                              void* d_out, int out_size) {
    const float* x    = (const float*)d_in[0];
    const float* W    = (const float*)d_in[1];
    const float* U    = (const float*)d_in[2];
    const float* bias = (const float*)d_in[3];
    float* out = (float*)d_out;

    const int smem1 = (2 * 128 * 36 + 2 * 32 * 132 + 128) * (int)sizeof(float);  // 71,168 B
    const int smem2 = (64 * HSTR + 16 * BSTR + 64 * 17) * (int)sizeof(float);    // 203,008 B
    cudaFuncSetAttribute(xw_gemm_tc, cudaFuncAttributeMaxDynamicSharedMemorySize, smem1);
    cudaFuncSetAttribute(lstm_rec, cudaFuncAttributeMaxDynamicSharedMemorySize, smem2);

    int has_hc = (out_size >= (int)((size_t)BZ * SQ * HD + 2 * BZ * HD)) ? 1 : 0;

    xw_gemm_tc<<<dim3(GT / 128, SQ / 2), 256, smem1>>>(x, W, bias);
    lstm_rec<<<NCTA, 256, smem2>>>(U, out, has_hc);
}